// round 15
// baseline (speedup 1.0000x reference)
#include <cuda_runtime.h>
#include <cuda_bf16.h>
#include <cstdint>

#define BB   64
#define TT_  64
#define GG   11
#define FF   4
#define HH   256
#define EE   128
#define NT   3
#define GT   (GG*BB)     // 704
#define MTOT (TT_*GT)    // 45056
#define NG   1024
#define KSZ  (256*1024)

#define ER 64
#define EC 128
#define BP 132
#define AP 132
#define SB_WORDS (2*128*BP)
#define SA_WORDS (2*64*AP)
#define SMEM_ENC ((SB_WORDS + SA_WORDS)*4)

#define DW_F   (2*32*128)
#define DIN_F  (16*260)
#define DE_F   (16*128)
#define SMEM_DEC ((DW_F + DIN_F + DE_F)*4)

__device__ float g_X[MTOT*NG];
__device__ float g_Y0[MTOT*HH];
__device__ float g_Cst[GT*HH];
__device__ __nv_bfloat16 g_Ahi[MTOT*HH];
__device__ __nv_bfloat16 g_Alo[MTOT*HH];
__device__ __nv_bfloat16 g_WihHi[(EE + 3*HH)*NG];
__device__ __nv_bfloat16 g_WihLo[(EE + 3*HH)*NG];
__device__ __nv_bfloat16 g_WhhHi[4*NG*HH];
__device__ __nv_bfloat16 g_WhhLo[4*NG*HH];
__device__ float g_biasEncP[4*NG];
__device__ float g_decWihsT[3*KSZ];
__device__ float g_decWhhT[3*KSZ];
__device__ float g_WcPack[512*NG];
__device__ float g_decWeT[EE*NG];
__device__ float g_biasDec[4*NG];
__device__ float g_dech[4*BB*HH];
__device__ float g_decc[4*BB*HH];
__device__ float g_attn[BB*HH];
__device__ float g_cin[BB*512];
__device__ float g_const[4*BB*NG];
__device__ float g_h1[NT*BB*HH];
__device__ float g_h2[NT*BB*HH];
// per-group barriers: 16 groups max, each (counter,flag) on its own 128B line
__device__ unsigned g_bcntA[16*32];
__device__ unsigned g_flagA[16*32];

__device__ __forceinline__ float ftanh(float x)
{
    float t;
    asm("tanh.approx.f32 %0, %1;" : "=f"(t) : "f"(x));
    return t;
}
__device__ __forceinline__ float fsig(float x)
{
    return fmaf(ftanh(0.5f*x), 0.5f, 0.5f);
}

__device__ __host__ __forceinline__ int permn(int n)
{
    int gate = n >> 8, h = n & 255;
    int hp = h >> 1, par = h & 1;
    return (hp >> 2)*32 + gate*8 + (hp & 3)*2 + par;
}

__global__ void reset_barrier_k()
{
    int i = threadIdx.x;
    if (i < 16*32){ g_bcntA[i] = 0; g_flagA[i] = 0; }
}

// per-group barrier: nb arrivals within group grp
__device__ __forceinline__ void group_barrier(unsigned nb, unsigned& round, int grp)
{
    __syncthreads();
    if (threadIdx.x == 0){
        unsigned target = ++round;
        unsigned* cnt = &g_bcntA[grp*32];
        unsigned* flg = &g_flagA[grp*32];
        __threadfence();
        unsigned old = atomicAdd(cnt, 1u);
        if (old == target*nb - 1u){
            asm volatile("st.release.gpu.global.u32 [%0], %1;"
                         :: "l"(flg), "r"(target) : "memory");
            __threadfence();
        } else {
            unsigned v;
            while (true){
                asm volatile("ld.acquire.gpu.global.u32 %0, [%1];"
                             : "=r"(v) : "l"(flg) : "memory");
                if (v >= target) break;
                __nanosleep(32);
            }
        }
    }
    __syncthreads();
}

__global__ void transpose_k(const float* __restrict__ src, int ldS, int rows, int cols,
                            float* __restrict__ dst, int ldD)
{
    __shared__ float tile[32][33];
    int c0 = blockIdx.x*32, r0 = blockIdx.y*32;
    for (int i = threadIdx.y; i < 32; i += 8){
        int r = r0 + i, c = c0 + threadIdx.x;
        tile[i][threadIdx.x] = (r < rows && c < cols) ? src[(size_t)r*ldS + c] : 0.f;
    }
    __syncthreads();
    for (int i = threadIdx.y; i < 32; i += 8){
        int c = c0 + i, r = r0 + threadIdx.x;
        if (c < cols && r < rows) dst[(size_t)c*ldD + r] = tile[threadIdx.x][i];
    }
}

__global__ void addv_k(const float* a, const float* b, float* o, int n)
{
    int i = blockIdx.x*256 + threadIdx.x;
    if (i < n) o[i] = a[i] + b[i];
}

__global__ void addv_perm_k(const float* __restrict__ a, const float* __restrict__ b,
                            float* __restrict__ o)
{
    int n = blockIdx.x*256 + threadIdx.x;
    if (n < NG) o[permn(n)] = a[n] + b[n];
}

__global__ void wsplit_perm_k(const float* __restrict__ src, int K,
                              __nv_bfloat16* __restrict__ hi, __nv_bfloat16* __restrict__ lo)
{
    int i = blockIdx.x*256 + threadIdx.x;
    if (i < NG*K){
        int n = i / K, k = i - n*K;
        float v = src[i];
        __nv_bfloat16 h = __float2bfloat16(v);
        int d = permn(n)*K + k;
        hi[d] = h;
        lo[d] = __float2bfloat16(v - __bfloat162float(h));
    }
}

__global__ void emb_k(const float* __restrict__ x, const float* __restrict__ W,
                      const float* __restrict__ bias,
                      __nv_bfloat16* __restrict__ hi, __nv_bfloat16* __restrict__ lo)
{
    int m = blockIdx.x;
    int t = m / GT; int rem = m % GT; int g = rem >> 6; int b = rem & 63;
    const float* xr = x + (((size_t)(b*TT_ + t))*GG + g)*FF;
    int e = threadIdx.x;
    float v = bias[e] + xr[0]*W[e*4] + xr[1]*W[e*4+1] + xr[2]*W[e*4+2] + xr[3]*W[e*4+3];
    v = fmaxf(v, 0.f);
    __nv_bfloat16 h = __float2bfloat16(v);
    hi[(size_t)m*EE + e] = h;
    lo[(size_t)m*EE + e] = __float2bfloat16(v - __bfloat162float(h));
}

__device__ __forceinline__ void mma_bf16(float* c, const uint32_t* a, uint32_t b0, uint32_t b1)
{
    asm volatile("mma.sync.aligned.m16n8k16.row.col.f32.bf16.bf16.f32 "
        "{%0,%1,%2,%3}, {%4,%5,%6,%7}, {%8,%9}, {%0,%1,%2,%3};"
        : "+f"(c[0]), "+f"(c[1]), "+f"(c[2]), "+f"(c[3])
        : "r"(a[0]), "r"(a[1]), "r"(a[2]), "r"(a[3]), "r"(b0), "r"(b1));
}

__global__ __launch_bounds__(256, 2) void gemm_tc_k(
    const __nv_bfloat16* __restrict__ Ahi, const __nv_bfloat16* __restrict__ Alo,
    const __nv_bfloat16* __restrict__ Whi, const __nv_bfloat16* __restrict__ Wlo,
    const float* __restrict__ bias, float* __restrict__ C, int K)
{
    __shared__ __align__(16) uint32_t sA[2][128][20];
    __shared__ __align__(16) uint32_t sB[2][128][20];
    const int tid = threadIdx.x;
    const int lane = tid & 31, wid = tid >> 5;
    const int wm = wid & 3, wn = wid >> 2;
    const int m0 = blockIdx.y*128, n0 = blockIdx.x*128;
    const int g = lane >> 2, q = lane & 3;
    float acc[2][8][4];
    #pragma unroll
    for (int i = 0; i < 2; i++)
        #pragma unroll
        for (int j = 0; j < 8; j++){ acc[i][j][0]=0.f; acc[i][j][1]=0.f; acc[i][j][2]=0.f; acc[i][j][3]=0.f; }

    for (int k0 = 0; k0 < K; k0 += 32){
        #pragma unroll
        for (int rep = 0; rep < 2; rep++){
            int chunk = tid + rep*256;
            int row = chunk >> 2, off = chunk & 3;
            size_t ga = (size_t)(m0 + row)*K + k0 + off*8;
            size_t gb = (size_t)(n0 + row)*K + k0 + off*8;
            *reinterpret_cast<uint4*>(&sA[0][row][off*4]) = *reinterpret_cast<const uint4*>(Ahi + ga);
            *reinterpret_cast<uint4*>(&sA[1][row][off*4]) = *reinterpret_cast<const uint4*>(Alo + ga);
            *reinterpret_cast<uint4*>(&sB[0][row][off*4]) = *reinterpret_cast<const uint4*>(Whi + gb);
            *reinterpret_cast<uint4*>(&sB[1][row][off*4]) = *reinterpret_cast<const uint4*>(Wlo + gb);
        }
        __syncthreads();
        #pragma unroll
        for (int ks = 0; ks < 2; ks++){
            int kp = q + ks*8;
            uint32_t a[2][2][4];
            #pragma unroll
            for (int fm = 0; fm < 2; fm++){
                int row = wm*32 + fm*16;
                #pragma unroll
                for (int s = 0; s < 2; s++){
                    a[fm][s][0] = sA[s][row+g][kp];
                    a[fm][s][1] = sA[s][row+g+8][kp];
                    a[fm][s][2] = sA[s][row+g][kp+4];
                    a[fm][s][3] = sA[s][row+g+8][kp+4];
                }
            }
            #pragma unroll
            for (int fn = 0; fn < 8; fn++){
                int nr = wn*64 + fn*8 + g;
                uint32_t bh0 = sB[0][nr][kp], bh1 = sB[0][nr][kp+4];
                uint32_t bl0 = sB[1][nr][kp], bl1 = sB[1][nr][kp+4];
                #pragma unroll
                for (int fm = 0; fm < 2; fm++){
                    mma_bf16(acc[fm][fn], a[fm][0], bh0, bh1);
                    mma_bf16(acc[fm][fn], a[fm][0], bl0, bl1);
                    mma_bf16(acc[fm][fn], a[fm][1], bh0, bh1);
                }
            }
        }
        __syncthreads();
    }
    #pragma unroll
    for (int fm = 0; fm < 2; fm++){
        int r = m0 + wm*32 + fm*16 + g;
        #pragma unroll
        for (int fn = 0; fn < 8; fn++){
            int cn = n0 + wn*64 + fn*8 + q*2;
            float b0 = bias[cn], b1 = bias[cn+1];
            float2 v0 = make_float2(acc[fm][fn][0] + b0, acc[fm][fn][1] + b1);
            float2 v1 = make_float2(acc[fm][fn][2] + b0, acc[fm][fn][3] + b1);
            *reinterpret_cast<float2*>(C + (size_t)r*NG + cn) = v0;
            *reinterpret_cast<float2*>(C + (size_t)(r+8)*NG + cn) = v1;
        }
    }
}

__global__ void gemm_k(const float* __restrict__ A, const float* __restrict__ B,
                       const float* __restrict__ bias, float* __restrict__ C,
                       int M, int N, int K)
{
    __shared__ float As[8][128];
    __shared__ float Bs[8][128];
    int tid = threadIdx.x;
    int m0 = blockIdx.y*128, n0 = blockIdx.x*128;
    int tx = tid & 15, ty = tid >> 4;
    float acc[8][8];
    #pragma unroll
    for (int i = 0; i < 8; i++)
        #pragma unroll
        for (int j = 0; j < 8; j++) acc[i][j] = 0.f;
    int arow = tid >> 1, acol = (tid & 1)*4;
    int brow = tid >> 5, bcol = (tid & 31)*4;
    for (int k0 = 0; k0 < K; k0 += 8){
        float4 av = make_float4(0.f,0.f,0.f,0.f);
        int gm = m0 + arow;
        if (gm < M) av = *reinterpret_cast<const float4*>(A + (size_t)gm*K + k0 + acol);
        As[acol+0][arow] = av.x; As[acol+1][arow] = av.y;
        As[acol+2][arow] = av.z; As[acol+3][arow] = av.w;
        *reinterpret_cast<float4*>(&Bs[brow][bcol]) =
            *reinterpret_cast<const float4*>(B + (size_t)(k0+brow)*N + n0 + bcol);
        __syncthreads();
        #pragma unroll
        for (int kk = 0; kk < 8; kk++){
            float a[8], b[8];
            *reinterpret_cast<float4*>(a)   = *reinterpret_cast<float4*>(&As[kk][ty*4]);
            *reinterpret_cast<float4*>(a+4) = *reinterpret_cast<float4*>(&As[kk][64+ty*4]);
            *reinterpret_cast<float4*>(b)   = *reinterpret_cast<float4*>(&Bs[kk][tx*4]);
            *reinterpret_cast<float4*>(b+4) = *reinterpret_cast<float4*>(&Bs[kk][64+tx*4]);
            #pragma unroll
            for (int i = 0; i < 8; i++)
                #pragma unroll
                for (int j = 0; j < 8; j++) acc[i][j] += a[i]*b[j];
        }
        __syncthreads();
    }
    #pragma unroll
    for (int i = 0; i < 8; i++){
        int gm = m0 + ((i < 4) ? (ty*4 + i) : (64 + ty*4 + (i-4)));
        if (gm >= M) continue;
        #pragma unroll
        for (int j = 0; j < 8; j++){
            int gn = n0 + ((j < 4) ? (tx*4 + j) : (64 + tx*4 + (j-4)));
            C[(size_t)gm*N + gn] = acc[i][j] + bias[gn];
        }
    }
}

// ---------------------------------------------------------------------------
// Persistent tc encoder layer: per-row-group barriers (11 groups x 8 blocks).
// ---------------------------------------------------------------------------
extern __shared__ uint32_t sdyn[];

__global__ void __launch_bounds__(256, 1) enc_tc_k(
    const float* __restrict__ X,
    const __nv_bfloat16* __restrict__ WHi, const __nv_bfloat16* __restrict__ WLo,
    float* __restrict__ Y, float* __restrict__ Cfin,
    __nv_bfloat16* __restrict__ Hhi, __nv_bfloat16* __restrict__ Hlo,
    int writeY)
{
    uint32_t* sB = sdyn;
    uint32_t* sA = sdyn + SB_WORDS;
    const int tid = threadIdx.x;
    const int lane = tid & 31, wid = tid >> 5;
    const int wm = wid & 1, wn = wid >> 1;
    const int g = lane >> 2, q = lane & 3;
    const int rt = blockIdx.x % 11, ct = blockIdx.x / 11;
    const int m0 = rt*ER, n0 = ct*EC;
    unsigned round = 0;

    for (int i = tid; i < 2*128*32; i += 256){
        int s = i >> 12;
        int rem = i & 4095;
        int row = rem >> 5, w4 = rem & 31;
        const uint4* src = reinterpret_cast<const uint4*>(
            (s ? WLo : WHi) + (size_t)(n0 + row)*HH) + w4;
        *reinterpret_cast<uint4*>(&sB[s*128*BP + row*BP + w4*4]) = *src;
    }
    __syncthreads();

    const int hg = ct*32 + wn*8 + q*2;
    float c[8];
    #pragma unroll
    for (int e = 0; e < 8; e++) c[e] = 0.f;

    for (int t = 0; t < 64; t++){
        float2 xv[2][2][4];
        #pragma unroll
        for (int fm = 0; fm < 2; fm++)
            #pragma unroll
            for (int rr = 0; rr < 2; rr++){
                int rglob = m0 + wm*32 + fm*16 + g + rr*8;
                const float* xp = X + ((size_t)t*GT + rglob)*NG + n0 + wn*32 + q*2;
                xv[fm][rr][0] = __ldcg(reinterpret_cast<const float2*>(xp));
                xv[fm][rr][1] = __ldcg(reinterpret_cast<const float2*>(xp + 8));
                xv[fm][rr][2] = __ldcg(reinterpret_cast<const float2*>(xp + 16));
                xv[fm][rr][3] = __ldcg(reinterpret_cast<const float2*>(xp + 24));
            }
        float acc[2][4][4];
        #pragma unroll
        for (int i = 0; i < 2; i++)
            #pragma unroll
            for (int j = 0; j < 4; j++){ acc[i][j][0]=0.f; acc[i][j][1]=0.f; acc[i][j][2]=0.f; acc[i][j][3]=0.f; }
        if (t > 0){
            for (int i = tid; i < 2*64*32; i += 256){
                int s = i >> 11;
                int rem = i & 2047;
                int row = rem >> 5, w4 = rem & 31;
                const uint4* src = reinterpret_cast<const uint4*>(
                    (s ? Hlo : Hhi) + ((size_t)(t-1)*GT + m0 + row)*HH) + w4;
                uint4 v = __ldcg(src);
                *reinterpret_cast<uint4*>(&sA[s*64*AP + row*AP + w4*4]) = v;
            }
            __syncthreads();
            #pragma unroll
            for (int ks = 0; ks < 16; ks++){
                const int kp = ks*8 + q;
                uint32_t a[2][2][4];
                #pragma unroll
                for (int fm = 0; fm < 2; fm++){
                    int row = wm*32 + fm*16;
                    #pragma unroll
                    for (int s = 0; s < 2; s++){
                        const uint32_t* base = sA + s*64*AP;
                        a[fm][s][0] = base[(row+g)*AP + kp];
                        a[fm][s][1] = base[(row+g+8)*AP + kp];
                        a[fm][s][2] = base[(row+g)*AP + kp+4];
                        a[fm][s][3] = base[(row+g+8)*AP + kp+4];
                    }
                }
                #pragma unroll
                for (int fn = 0; fn < 4; fn++){
                    int nr = wn*32 + fn*8 + g;
                    uint32_t bh0 = sB[nr*BP + kp], bh1 = sB[nr*BP + kp+4];
                    uint32_t bl0 = sB[128*BP + nr*BP + kp], bl1 = sB[128*BP + nr*BP + kp+4];
                    #pragma unroll
                    for (int fm = 0; fm < 2; fm++){
                        mma_bf16(acc[fm][fn], a[fm][0], bh0, bh1);
                        mma_bf16(acc[fm][fn], a[fm][0], bl0, bl1);
                        mma_bf16(acc[fm][fn], a[fm][1], bh0, bh1);
                    }
                }
            }
        }
        const int doY = (writeY || t == 63);
        #pragma unroll
        for (int fm = 0; fm < 2; fm++){
            #pragma unroll
            for (int rr = 0; rr < 2; rr++){
                int rglob = m0 + wm*32 + fm*16 + g + rr*8;
                int kp = rr*2;
                float gi0 = acc[fm][0][kp]   + xv[fm][rr][0].x;
                float gi1 = acc[fm][0][kp+1] + xv[fm][rr][0].y;
                float gf0 = acc[fm][1][kp]   + xv[fm][rr][1].x;
                float gf1 = acc[fm][1][kp+1] + xv[fm][rr][1].y;
                float gg0 = acc[fm][2][kp]   + xv[fm][rr][2].x;
                float gg1 = acc[fm][2][kp+1] + xv[fm][rr][2].y;
                float go0 = acc[fm][3][kp]   + xv[fm][rr][3].x;
                float go1 = acc[fm][3][kp+1] + xv[fm][rr][3].y;
                int ci = fm*4 + rr*2;
                float c0 = fsig(gf0)*c[ci]   + fsig(gi0)*ftanh(gg0);
                float c1 = fsig(gf1)*c[ci+1] + fsig(gi1)*ftanh(gg1);
                c[ci] = c0; c[ci+1] = c1;
                float h0 = fsig(go0)*ftanh(c0);
                float h1 = fsig(go1)*ftanh(c1);
                size_t yb = ((size_t)t*GT + rglob)*HH + hg;
                if (doY) *reinterpret_cast<float2*>(Y + yb) = make_float2(h0, h1);
                __nv_bfloat16 b0 = __float2bfloat16(h0), b1 = __float2bfloat16(h1);
                __nv_bfloat162 hhv; hhv.x = b0; hhv.y = b1;
                __nv_bfloat162 llv;
                llv.x = __float2bfloat16(h0 - __bfloat162float(b0));
                llv.y = __float2bfloat16(h1 - __bfloat162float(b1));
                *reinterpret_cast<__nv_bfloat162*>(Hhi + yb) = hhv;
                *reinterpret_cast<__nv_bfloat162*>(Hlo + yb) = llv;
            }
        }
        group_barrier(8, round, rt);    // only same-rt blocks must sync
    }
    #pragma unroll
    for (int fm = 0; fm < 2; fm++)
        #pragma unroll
        for (int rr = 0; rr < 2; rr++){
            int rglob = m0 + wm*32 + fm*16 + g + rr*8;
            int ci = fm*4 + rr*2;
            *reinterpret_cast<float2*>(Cfin + (size_t)rglob*HH + hg) =
                make_float2(c[ci], c[ci+1]);
        }
}

__global__ void snap_k(const float* __restrict__ Yt, const float* __restrict__ C,
                       const int* __restrict__ tord, float* dh, float* dc)
{
    int b = blockIdx.x, h = threadIdx.x;
    int row = (*tord)*64 + b;
    dh[b*HH + h] = Yt[(size_t)row*HH + h];
    dc[b*HH + h] = C[(size_t)row*HH + h];
}

__global__ void attn_k(const float* __restrict__ Y3, const float* __restrict__ attnW,
                       float* __restrict__ attn)
{
    int b = blockIdx.x, tid = threadIdx.x;
    __shared__ float wae[HH];
    __shared__ float sc[GT];
    __shared__ float red[256];
    wae[tid] = attnW[HH + tid];
    __syncthreads();
    for (int idx = tid; idx < GT; idx += 256){
        int g = idx % GG, t = idx / GG;
        const float* row = Y3 + ((size_t)(t*GT + g*64 + b))*HH;
        float s = 0.f;
        #pragma unroll 4
        for (int h = 0; h < HH; h++) s += row[h]*wae[h];
        sc[idx] = s;
    }
    __syncthreads();
    float mx = -1e30f;
    for (int idx = tid; idx < GT; idx += 256) mx = fmaxf(mx, sc[idx]);
    red[tid] = mx; __syncthreads();
    for (int s = 128; s > 0; s >>= 1){ if (tid < s) red[tid] = fmaxf(red[tid], red[tid+s]); __syncthreads(); }
    mx = red[0]; __syncthreads();
    float sm = 0.f;
    for (int idx = tid; idx < GT; idx += 256){ float e = __expf(sc[idx]-mx); sc[idx] = e; sm += e; }
    red[tid] = sm; __syncthreads();
    for (int s = 128; s > 0; s >>= 1){ if (tid < s) red[tid] += red[tid+s]; __syncthreads(); }
    float inv = __fdividef(1.f, red[0]);
    __syncthreads();
    float a0 = 0.f;
    for (int idx = 0; idx < GT; idx++){
        int g = idx % GG, t = idx / GG;
        a0 += sc[idx]*Y3[((size_t)(t*GT + g*64 + b))*HH + tid];
    }
    attn[b*HH + tid] = a0*inv;
}

__global__ void pack_cin_k(const float* dh0, const float* attn, float* cin)
{
    int b = blockIdx.x, k = threadIdx.x;
    cin[b*512 + k] = (k < HH) ? dh0[b*HH + k] : attn[b*HH + (k - HH)];
}

// ---------------------------------------------------------------------------
// Persistent decoder: per-m-tile barriers (12 groups x 8 blocks).
// ---------------------------------------------------------------------------
__global__ __launch_bounds__(256, 2) void dec_persist_k(
    const float* __restrict__ x, const int* __restrict__ tord,
    const float* __restrict__ cnst, const float* __restrict__ cinAll,
    const float* __restrict__ WeT, const float* __restrict__ WihsT,
    float* __restrict__ H1, float* __restrict__ H2,
    const float* __restrict__ outW, const float* __restrict__ outB,
    const float* __restrict__ Wemb, const float* __restrict__ bemb,
    float* __restrict__ dout)
{
    float* sW   = reinterpret_cast<float*>(sdyn);
    float* sInF = sW + DW_F;
    float* sE   = sInF + DIN_F;
    __shared__ float sRed[16][16];
    __shared__ float sOut[16][4];
    const int tid = threadIdx.x;
    const int tx = tid & 31, ty = tid >> 5;
    const int jc = blockIdx.x & 7;
    const int mt = blockIdx.x >> 3;
    const int m0 = mt*16, j0 = jc*32;
    unsigned round = 0;
    const int tordv = *tord;
    const int j = j0 + tx;
    const int wrow = tid >> 5, wc4 = tid & 31;
    const size_t wcol = (size_t)(wc4 >> 3)*HH + j0 + (wc4 & 7)*4;

    for (int t = 0; t < 64; t++){
        if (t == 0){
            for (int idx = tid; idx < 16*128; idx += 256){
                int rr = idx >> 7, e = idx & 127;
                int m = m0 + rr;
                const float* xr = x + (((size_t)((m & 63)*TT_ + 63))*GG + (tordv + (m >> 6)))*FF;
                float v = bemb[e] + xr[0]*Wemb[e*4] + xr[1]*Wemb[e*4+1]
                                  + xr[2]*Wemb[e*4+2] + xr[3]*Wemb[e*4+3];
                sE[rr*128 + e] = fmaxf(v, 0.f);
            }
            __syncthreads();
        } else {
            {
                int r = tid >> 4, sub = tid & 15, o = sub & 3, seg = sub >> 2;
                const float* hrow = H2 + (size_t)(m0 + r)*HH;
                float s = 0.f;
                #pragma unroll 4
                for (int h = seg*64; h < seg*64 + 64; h++)
                    s += __ldcg(hrow + h) * outW[o*HH + h];
                sRed[r][sub] = s;
            }
            __syncthreads();
            if (tid < 64){
                int rr = tid >> 2, oo = tid & 3;
                float v = sRed[rr][oo] + sRed[rr][4+oo] + sRed[rr][8+oo] + sRed[rr][12+oo] + outB[oo];
                sOut[rr][oo] = v;
                if (jc == 0){
                    int m = m0 + rr;
                    dout[(size_t)(m & 63)*(TT_*NT*FF) + (size_t)(t-1)*(NT*FF) + (m >> 6)*FF + oo] = v;
                }
            }
            __syncthreads();
            for (int idx = tid; idx < 16*128; idx += 256){
                int rr = idx >> 7, e = idx & 127;
                float v = bemb[e] + sOut[rr][0]*Wemb[e*4] + sOut[rr][1]*Wemb[e*4+1]
                        + sOut[rr][2]*Wemb[e*4+2] + sOut[rr][3]*Wemb[e*4+3];
                sE[rr*128 + e] = fmaxf(v, 0.f);
            }
            __syncthreads();
        }
        for (int l = 0; l < 4; l++){
            const float* Wt = (l == 0) ? WeT : (WihsT + (size_t)(l-1)*KSZ);
            const int K = (l == 0) ? EE : HH;
            const int nch = K >> 5;
            const float* In = (l == 2) ? H2 : H1;
            float* Ho = (l == 0 || l == 2) ? H1 : H2;
            float4 wreg[4];
            #pragma unroll
            for (int r = 0; r < 4; r++)
                wreg[r] = __ldcg(reinterpret_cast<const float4*>(
                    Wt + (size_t)(wrow + r*8)*NG + wcol));
            if (l > 0){
                #pragma unroll
                for (int r = 0; r < 4; r++){
                    int i = r*256 + tid, row = i >> 6, c4 = i & 63;
                    float4 v = __ldcg(reinterpret_cast<const float4*>(
                        In + (size_t)(m0 + row)*HH + c4*4));
                    *reinterpret_cast<float4*>(&sInF[row*260 + c4*4]) = v;
                }
            }
            #pragma unroll
            for (int r = 0; r < 4; r++)
                *reinterpret_cast<float4*>(&sW[(wrow + r*8)*128 + wc4*4]) = wreg[r];
            __syncthreads();
            float acc[2][4] = {{0.f,0.f,0.f,0.f},{0.f,0.f,0.f,0.f}};
            const float* aIn = (l == 0) ? sE : sInF;
            const int aPitch = (l == 0) ? 128 : 260;
            for (int ch = 0; ch < nch; ch++){
                if (ch + 1 < nch){
                    #pragma unroll
                    for (int r = 0; r < 4; r++)
                        wreg[r] = __ldcg(reinterpret_cast<const float4*>(
                            Wt + (size_t)((ch+1)*32 + wrow + r*8)*NG + wcol));
                }
                const float* wb = sW + (size_t)(ch & 1)*32*128;
                const float* a0p = aIn + (ty*2)*aPitch + ch*32;
                const float* a1p = aIn + (ty*2+1)*aPitch + ch*32;
                #pragma unroll
                for (int kk = 0; kk < 32; kk++){
                    const float* wr = wb + kk*128;
                    float w0 = wr[tx], w1 = wr[32+tx], w2 = wr[64+tx], w3 = wr[96+tx];
                    float a0 = a0p[kk], a1 = a1p[kk];
                    acc[0][0]+=a0*w0; acc[0][1]+=a0*w1; acc[0][2]+=a0*w2; acc[0][3]+=a0*w3;
                    acc[1][0]+=a1*w0; acc[1][1]+=a1*w1; acc[1][2]+=a1*w2; acc[1][3]+=a1*w3;
                }
                if (ch + 1 < nch){
                    #pragma unroll
                    for (int r = 0; r < 4; r++)
                        *reinterpret_cast<float4*>(&sW[((ch+1)&1)*32*128 + (wrow + r*8)*128 + wc4*4]) = wreg[r];
                    __syncthreads();
                }
            }
            const float* cl = cnst + (size_t)l*BB*NG;
            const float* ci = cinAll + (size_t)l*BB*HH;
            #pragma unroll
            for (int rr = 0; rr < 2; rr++){
                int m = m0 + ty*2 + rr, b = m & 63;
                const float* cp = cl + (size_t)b*NG;
                float gi = acc[rr][0] + cp[j];
                float gf = acc[rr][1] + cp[HH + j];
                float gg = acc[rr][2] + cp[2*HH + j];
                float go = acc[rr][3] + cp[3*HH + j];
                float c2 = fsig(gf)*ci[b*HH + j] + fsig(gi)*ftanh(gg);
                Ho[(size_t)m*HH + j] = fsig(go)*ftanh(c2);
            }
            group_barrier(8, round, 4 + mt);   // groups 4..15 (disjoint from enc use)
        }
    }
    {
        int r = tid >> 4, sub = tid & 15, o = sub & 3, seg = sub >> 2;
        const float* hrow = H2 + (size_t)(m0 + r)*HH;
        float s = 0.f;
        #pragma unroll 4
        for (int h = seg*64; h < seg*64 + 64; h++)
            s += __ldcg(hrow + h) * outW[o*HH + h];
        sRed[r][sub] = s;
    }
    __syncthreads();
    if (tid < 64 && jc == 0){
        int rr = tid >> 2, oo = tid & 3;
        float v = sRed[rr][oo] + sRed[rr][4+oo] + sRed[rr][8+oo] + sRed[rr][12+oo] + outB[oo];
        int m = m0 + rr;
        dout[(size_t)(m & 63)*(TT_*NT*FF) + 63u*(NT*FF) + (m >> 6)*FF + oo] = v;
    }
}

static float* symaddr(const void* sym)
{
    void* p = nullptr;
    cudaGetSymbolAddress(&p, sym);
    return (float*)p;
}

extern "C" void kernel_launch(void* const* d_in, const int* in_sizes, int n_in,
                              void* d_out, int out_size)
{
    (void)in_sizes; (void)n_in; (void)out_size;
    const float* x       = (const float*)d_in[0];
    const float* encLinW = (const float*)d_in[2];
    const float* encLinB = (const float*)d_in[3];
    const float* encWih0 = (const float*)d_in[4];
    const float* encWihs = (const float*)d_in[5];
    const float* encWhh  = (const float*)d_in[6];
    const float* encBih  = (const float*)d_in[7];
    const float* encBhh  = (const float*)d_in[8];
    const float* decEmbW = (const float*)d_in[9];
    const float* decEmbB = (const float*)d_in[10];
    const float* attnW   = (const float*)d_in[11];
    const float* decWih0 = (const float*)d_in[13];
    const float* decWihs = (const float*)d_in[14];
    const float* decWhh  = (const float*)d_in[15];
    const float* decBih  = (const float*)d_in[16];
    const float* decBhh  = (const float*)d_in[17];
    const float* outW    = (const float*)d_in[18];
    const float* outB    = (const float*)d_in[19];
    const int*   tord    = (const int*)d_in[20];
    float* out = (float*)d_out;

    float* pX = symaddr(g_X);
    float* pY = symaddr(g_Y0);
    float* pC = symaddr(g_Cst);
    __nv_bfloat16* pAhi = (__nv_bfloat16*)symaddr(g_Ahi);
    __nv_bfloat16* pAlo = (__nv_bfloat16*)symaddr(g_Alo);
    __nv_bfloat16* pWihHi = (__nv_bfloat16*)symaddr(g_WihHi);
    __nv_bfloat16* pWihLo = (__nv_bfloat16*)symaddr(g_WihLo);
    __nv_bfloat16* pWhhHi = (__nv_bfloat16*)symaddr(g_WhhHi);
    __nv_bfloat16* pWhhLo = (__nv_bfloat16*)symaddr(g_WhhLo);
    float* pBiasEncP = symaddr(g_biasEncP);
    float* pDecWihsT = symaddr(g_decWihsT);
    float* pDecWhhT = symaddr(g_decWhhT);
    float* pPack = symaddr(g_WcPack);
    float* pWeT = symaddr(g_decWeT);
    float* pBiasDec = symaddr(g_biasDec);
    float* pDech = symaddr(g_dech);
    float* pDecc = symaddr(g_decc);
    float* pAttn = symaddr(g_attn);
    float* pCin = symaddr(g_cin);
    float* pConst = symaddr(g_const);
    float* pH1 = symaddr(g_h1);
    float* pH2 = symaddr(g_h2);

    cudaFuncSetAttribute(enc_tc_k, cudaFuncAttributeMaxDynamicSharedMemorySize, SMEM_ENC);
    cudaFuncSetAttribute(dec_persist_k, cudaFuncAttributeMaxDynamicSharedMemorySize, SMEM_DEC);

    dim3 tb(32, 8);
    wsplit_perm_k<<<(NG*EE + 255)/256, 256>>>(encWih0, EE, pWihHi, pWihLo);
    for (int l = 1; l < 4; l++)
        wsplit_perm_k<<<(NG*HH + 255)/256, 256>>>(encWihs + (size_t)(l-1)*NG*HH, HH,
                                                  pWihHi + NG*EE + (size_t)(l-1)*NG*HH,
                                                  pWihLo + NG*EE + (size_t)(l-1)*NG*HH);
    for (int l = 0; l < 4; l++)
        wsplit_perm_k<<<(NG*HH + 255)/256, 256>>>(encWhh + (size_t)l*NG*HH, HH,
                                                  pWhhHi + (size_t)l*NG*HH,
                                                  pWhhLo + (size_t)l*NG*HH);
    for (int l = 0; l < 4; l++)
        addv_perm_k<<<4, 256>>>(encBih + l*NG, encBhh + l*NG, pBiasEncP + l*NG);
    for (int l = 0; l < 3; l++)
        transpose_k<<<dim3(8, 32), tb>>>(decWihs + (size_t)l*NG*HH, HH, NG, HH, pDecWihsT + (size_t)l*KSZ, NG);
    for (int l = 1; l < 4; l++)
        transpose_k<<<dim3(8, 32), tb>>>(decWhh + (size_t)l*NG*HH, HH, NG, HH, pDecWhhT + (size_t)(l-1)*KSZ, NG);
    transpose_k<<<dim3(8, 32), tb>>>(decWhh, HH, NG, HH, pPack, NG);
    transpose_k<<<dim3(8, 32), tb>>>(decWih0, 384, NG, HH, pPack + (size_t)HH*NG, NG);
    transpose_k<<<dim3(4, 32), tb>>>(decWih0 + HH, 384, NG, EE, pWeT, NG);
    addv_k<<<16, 256>>>(decBih, decBhh, pBiasDec, 4*NG);

    emb_k<<<MTOT, 128>>>(x, encLinW, encLinB, pAhi, pAlo);

    for (int l = 0; l < 4; l++){
        const __nv_bfloat16* wh = (l == 0) ? pWihHi : (pWihHi + NG*EE + (size_t)(l-1)*NG*HH);
        const __nv_bfloat16* wl = (l == 0) ? pWihLo : (pWihLo + NG*EE + (size_t)(l-1)*NG*HH);
        int Kin = (l == 0) ? EE : HH;
        gemm_tc_k<<<dim3(8, MTOT/128), 256>>>(pAhi, pAlo, wh, wl, pBiasEncP + l*NG, pX, Kin);
        reset_barrier_k<<<1, 512>>>();
        enc_tc_k<<<88, 256, SMEM_ENC>>>(pX, pWhhHi + (size_t)l*NG*HH, pWhhLo + (size_t)l*NG*HH,
                                        pY, pC, pAhi, pAlo, (l == 3) ? 1 : 0);
        snap_k<<<64, 256>>>(pY + (size_t)(TT_-1)*GT*HH, pC, tord,
                            pDech + (size_t)l*BB*HH, pDecc + (size_t)l*BB*HH);
    }

    attn_k<<<BB, 256>>>(pY, attnW, pAttn);
    pack_cin_k<<<BB, 512>>>(pDech, pAttn, pCin);
    gemm_k<<<dim3(8, 1), 256>>>(pCin, pPack, pBiasDec, pConst, BB, NG, 512);
    for (int l = 1; l < 4; l++)
        gemm_k<<<dim3(8, 1), 256>>>(pDech + (size_t)l*BB*HH, pDecWhhT + (size_t)(l-1)*KSZ,
                                    pBiasDec + l*NG, pConst + (size_t)l*BB*NG, BB, NG, HH);

    reset_barrier_k<<<1, 512>>>();
    dec_persist_k<<<96, 256, SMEM_DEC>>>(x, tord, pConst, pDecc, pWeT, pDecWihsT,
                                         pH1, pH2, outW, outB, decEmbW, decEmbB, out);
}

// round 16
// speedup vs baseline: 1.0447x; 1.0447x over previous
#include <cuda_runtime.h>
#include <cuda_bf16.h>
#include <cstdint>

#define BB   64
#define TT_  64
#define GG   11
#define FF   4
#define HH   256
#define EE   128
#define NT   3
#define GT   (GG*BB)     // 704
#define MTOT (TT_*GT)    // 45056
#define NG   1024
#define KSZ  (256*1024)

#define ER 64
#define EC 128
#define BP 132
#define AP 132
#define SB_WORDS (2*128*BP)
#define SA_WORDS (2*64*AP)
#define SMEM_ENC ((SB_WORDS + SA_WORDS)*4)

#define DW_F   (2*32*128)
#define DIN_F  (16*260)
#define DE_F   (16*128)
#define SMEM_DEC ((DW_F + DIN_F + DE_F)*4)

// gemm_tc double-buffered staging
#define GW_PLANE 2560                 // 128 rows x 20 words
#define GW_BUF   (4*GW_PLANE)         // Ahi|Alo|Bhi|Blo
#define SMEM_GEMM (2*GW_BUF*4)        // 81920 B

__device__ float g_X[MTOT*NG];
__device__ float g_Y0[MTOT*HH];
__device__ float g_Cst[GT*HH];
__device__ __nv_bfloat16 g_Ahi[MTOT*HH];
__device__ __nv_bfloat16 g_Alo[MTOT*HH];
__device__ __nv_bfloat16 g_WihHi[(EE + 3*HH)*NG];
__device__ __nv_bfloat16 g_WihLo[(EE + 3*HH)*NG];
__device__ __nv_bfloat16 g_WhhHi[4*NG*HH];
__device__ __nv_bfloat16 g_WhhLo[4*NG*HH];
__device__ float g_biasEncP[4*NG];
__device__ float g_decWihsT[3*KSZ];
__device__ float g_decWhhT[3*KSZ];
__device__ float g_WcPack[512*NG];
__device__ float g_decWeT[EE*NG];
__device__ float g_biasDec[4*NG];
__device__ float g_dech[4*BB*HH];
__device__ float g_decc[4*BB*HH];
__device__ float g_attn[BB*HH];
__device__ float g_cin[BB*512];
__device__ float g_const[4*BB*NG];
__device__ float g_h1[NT*BB*HH];
__device__ float g_h2[NT*BB*HH];
__device__ unsigned g_bcnt = 0;
__device__ unsigned g_flag = 0;

__device__ __forceinline__ float ftanh(float x)
{
    float t;
    asm("tanh.approx.f32 %0, %1;" : "=f"(t) : "f"(x));
    return t;
}
__device__ __forceinline__ float fsig(float x)
{
    return fmaf(ftanh(0.5f*x), 0.5f, 0.5f);
}

__device__ __host__ __forceinline__ int permn(int n)
{
    int gate = n >> 8, h = n & 255;
    int hp = h >> 1, par = h & 1;
    return (hp >> 2)*32 + gate*8 + (hp & 3)*2 + par;
}

__global__ void reset_barrier_k(){ g_bcnt = 0; g_flag = 0; }

__device__ __forceinline__ void grid_barrier(unsigned nb, unsigned& round)
{
    __syncthreads();
    if (threadIdx.x == 0){
        unsigned target = ++round;
        __threadfence();
        unsigned old = atomicAdd(&g_bcnt, 1u);
        if (old == target*nb - 1u){
            asm volatile("st.release.gpu.global.u32 [%0], %1;"
                         :: "l"(&g_flag), "r"(target) : "memory");
            __threadfence();
        } else {
            unsigned v;
            while (true){
                asm volatile("ld.acquire.gpu.global.u32 %0, [%1];"
                             : "=r"(v) : "l"(&g_flag) : "memory");
                if (v >= target) break;
                __nanosleep(32);
            }
        }
    }
    __syncthreads();
}

__device__ __forceinline__ void cp_async16(unsigned saddr, const void* gptr)
{
    asm volatile("cp.async.cg.shared.global [%0], [%1], 16;"
                 :: "r"(saddr), "l"(gptr));
}

__global__ void transpose_k(const float* __restrict__ src, int ldS, int rows, int cols,
                            float* __restrict__ dst, int ldD)
{
    __shared__ float tile[32][33];
    int c0 = blockIdx.x*32, r0 = blockIdx.y*32;
    for (int i = threadIdx.y; i < 32; i += 8){
        int r = r0 + i, c = c0 + threadIdx.x;
        tile[i][threadIdx.x] = (r < rows && c < cols) ? src[(size_t)r*ldS + c] : 0.f;
    }
    __syncthreads();
    for (int i = threadIdx.y; i < 32; i += 8){
        int c = c0 + i, r = r0 + threadIdx.x;
        if (c < cols && r < rows) dst[(size_t)c*ldD + r] = tile[threadIdx.x][i];
    }
}

__global__ void addv_k(const float* a, const float* b, float* o, int n)
{
    int i = blockIdx.x*256 + threadIdx.x;
    if (i < n) o[i] = a[i] + b[i];
}

__global__ void addv_perm_k(const float* __restrict__ a, const float* __restrict__ b,
                            float* __restrict__ o)
{
    int n = blockIdx.x*256 + threadIdx.x;
    if (n < NG) o[permn(n)] = a[n] + b[n];
}

__global__ void wsplit_perm_k(const float* __restrict__ src, int K,
                              __nv_bfloat16* __restrict__ hi, __nv_bfloat16* __restrict__ lo)
{
    int i = blockIdx.x*256 + threadIdx.x;
    if (i < NG*K){
        int n = i / K, k = i - n*K;
        float v = src[i];
        __nv_bfloat16 h = __float2bfloat16(v);
        int d = permn(n)*K + k;
        hi[d] = h;
        lo[d] = __float2bfloat16(v - __bfloat162float(h));
    }
}

__global__ void emb_k(const float* __restrict__ x, const float* __restrict__ W,
                      const float* __restrict__ bias,
                      __nv_bfloat16* __restrict__ hi, __nv_bfloat16* __restrict__ lo)
{
    int m = blockIdx.x;
    int t = m / GT; int rem = m % GT; int g = rem >> 6; int b = rem & 63;
    const float* xr = x + (((size_t)(b*TT_ + t))*GG + g)*FF;
    int e = threadIdx.x;
    float v = bias[e] + xr[0]*W[e*4] + xr[1]*W[e*4+1] + xr[2]*W[e*4+2] + xr[3]*W[e*4+3];
    v = fmaxf(v, 0.f);
    __nv_bfloat16 h = __float2bfloat16(v);
    hi[(size_t)m*EE + e] = h;
    lo[(size_t)m*EE + e] = __float2bfloat16(v - __bfloat162float(h));
}

__device__ __forceinline__ void mma_bf16(float* c, const uint32_t* a, uint32_t b0, uint32_t b1)
{
    asm volatile("mma.sync.aligned.m16n8k16.row.col.f32.bf16.bf16.f32 "
        "{%0,%1,%2,%3}, {%4,%5,%6,%7}, {%8,%9}, {%0,%1,%2,%3};"
        : "+f"(c[0]), "+f"(c[1]), "+f"(c[2]), "+f"(c[3])
        : "r"(a[0]), "r"(a[1]), "r"(a[2]), "r"(a[3]), "r"(b0), "r"(b1));
}

extern __shared__ uint32_t sdyn[];

// Tensor-core split-bf16 GEMM, cp.async double-buffered.
__global__ __launch_bounds__(256, 2) void gemm_tc_k(
    const __nv_bfloat16* __restrict__ Ahi, const __nv_bfloat16* __restrict__ Alo,
    const __nv_bfloat16* __restrict__ Whi, const __nv_bfloat16* __restrict__ Wlo,
    const float* __restrict__ bias, float* __restrict__ C, int K)
{
    const int tid = threadIdx.x;
    const int lane = tid & 31, wid = tid >> 5;
    const int wm = wid & 3, wn = wid >> 2;
    const int m0 = blockIdx.y*128, n0 = blockIdx.x*128;
    const int g = lane >> 2, q = lane & 3;
    const unsigned sbase = (unsigned)__cvta_generic_to_shared(sdyn);
    float acc[2][8][4];
    #pragma unroll
    for (int i = 0; i < 2; i++)
        #pragma unroll
        for (int j = 0; j < 8; j++){ acc[i][j][0]=0.f; acc[i][j][1]=0.f; acc[i][j][2]=0.f; acc[i][j][3]=0.f; }

    const int nch = K >> 5;
    // issue chunk kc into buffer (kc&1)
    auto issue = [&](int kc){
        int k0 = kc*32;
        unsigned bb = sbase + (unsigned)((kc & 1)*GW_BUF)*4u;
        #pragma unroll
        for (int rep = 0; rep < 2; rep++){
            int chunk = tid + rep*256;
            int row = chunk >> 2, off = chunk & 3;
            size_t ga = (size_t)(m0 + row)*K + k0 + off*8;
            size_t gb = (size_t)(n0 + row)*K + k0 + off*8;
            unsigned so = (unsigned)(row*20 + off*4)*4u;
            cp_async16(bb + so,                      Ahi + ga);
            cp_async16(bb + so + GW_PLANE*4u,        Alo + ga);
            cp_async16(bb + so + 2u*GW_PLANE*4u,     Whi + gb);
            cp_async16(bb + so + 3u*GW_PLANE*4u,     Wlo + gb);
        }
        asm volatile("cp.async.commit_group;");
    };

    issue(0);
    for (int kc = 0; kc < nch; kc++){
        if (kc + 1 < nch){
            issue(kc + 1);
            asm volatile("cp.async.wait_group 1;");
        } else {
            asm volatile("cp.async.wait_group 0;");
        }
        __syncthreads();
        const uint32_t* buf = sdyn + (kc & 1)*GW_BUF;
        #pragma unroll
        for (int ks = 0; ks < 2; ks++){
            int kp = q + ks*8;
            uint32_t a[2][2][4];
            #pragma unroll
            for (int fm = 0; fm < 2; fm++){
                int row = wm*32 + fm*16;
                #pragma unroll
                for (int s = 0; s < 2; s++){
                    const uint32_t* pl = buf + s*GW_PLANE;
                    a[fm][s][0] = pl[(row+g)*20 + kp];
                    a[fm][s][1] = pl[(row+g+8)*20 + kp];
                    a[fm][s][2] = pl[(row+g)*20 + kp+4];
                    a[fm][s][3] = pl[(row+g+8)*20 + kp+4];
                }
            }
            #pragma unroll
            for (int fn = 0; fn < 8; fn++){
                int nr = wn*64 + fn*8 + g;
                const uint32_t* bh = buf + 2*GW_PLANE;
                const uint32_t* bl = buf + 3*GW_PLANE;
                uint32_t bh0 = bh[nr*20 + kp], bh1 = bh[nr*20 + kp+4];
                uint32_t bl0 = bl[nr*20 + kp], bl1 = bl[nr*20 + kp+4];
                #pragma unroll
                for (int fm = 0; fm < 2; fm++){
                    mma_bf16(acc[fm][fn], a[fm][0], bh0, bh1);
                    mma_bf16(acc[fm][fn], a[fm][0], bl0, bl1);
                    mma_bf16(acc[fm][fn], a[fm][1], bh0, bh1);
                }
            }
        }
        __syncthreads();
    }
    #pragma unroll
    for (int fm = 0; fm < 2; fm++){
        int r = m0 + wm*32 + fm*16 + g;
        #pragma unroll
        for (int fn = 0; fn < 8; fn++){
            int cn = n0 + wn*64 + fn*8 + q*2;
            float b0 = bias[cn], b1 = bias[cn+1];
            float2 v0 = make_float2(acc[fm][fn][0] + b0, acc[fm][fn][1] + b1);
            float2 v1 = make_float2(acc[fm][fn][2] + b0, acc[fm][fn][3] + b1);
            *reinterpret_cast<float2*>(C + (size_t)r*NG + cn) = v0;
            *reinterpret_cast<float2*>(C + (size_t)(r+8)*NG + cn) = v1;
        }
    }
}

// fp32 GEMM (decoder constants)
__global__ void gemm_k(const float* __restrict__ A, const float* __restrict__ B,
                       const float* __restrict__ bias, float* __restrict__ C,
                       int M, int N, int K)
{
    __shared__ float As[8][128];
    __shared__ float Bs[8][128];
    int tid = threadIdx.x;
    int m0 = blockIdx.y*128, n0 = blockIdx.x*128;
    int tx = tid & 15, ty = tid >> 4;
    float acc[8][8];
    #pragma unroll
    for (int i = 0; i < 8; i++)
        #pragma unroll
        for (int j = 0; j < 8; j++) acc[i][j] = 0.f;
    int arow = tid >> 1, acol = (tid & 1)*4;
    int brow = tid >> 5, bcol = (tid & 31)*4;
    for (int k0 = 0; k0 < K; k0 += 8){
        float4 av = make_float4(0.f,0.f,0.f,0.f);
        int gm = m0 + arow;
        if (gm < M) av = *reinterpret_cast<const float4*>(A + (size_t)gm*K + k0 + acol);
        As[acol+0][arow] = av.x; As[acol+1][arow] = av.y;
        As[acol+2][arow] = av.z; As[acol+3][arow] = av.w;
        *reinterpret_cast<float4*>(&Bs[brow][bcol]) =
            *reinterpret_cast<const float4*>(B + (size_t)(k0+brow)*N + n0 + bcol);
        __syncthreads();
        #pragma unroll
        for (int kk = 0; kk < 8; kk++){
            float a[8], b[8];
            *reinterpret_cast<float4*>(a)   = *reinterpret_cast<float4*>(&As[kk][ty*4]);
            *reinterpret_cast<float4*>(a+4) = *reinterpret_cast<float4*>(&As[kk][64+ty*4]);
            *reinterpret_cast<float4*>(b)   = *reinterpret_cast<float4*>(&Bs[kk][tx*4]);
            *reinterpret_cast<float4*>(b+4) = *reinterpret_cast<float4*>(&Bs[kk][64+tx*4]);
            #pragma unroll
            for (int i = 0; i < 8; i++)
                #pragma unroll
                for (int j = 0; j < 8; j++) acc[i][j] += a[i]*b[j];
        }
        __syncthreads();
    }
    #pragma unroll
    for (int i = 0; i < 8; i++){
        int gm = m0 + ((i < 4) ? (ty*4 + i) : (64 + ty*4 + (i-4)));
        if (gm >= M) continue;
        #pragma unroll
        for (int j = 0; j < 8; j++){
            int gn = n0 + ((j < 4) ? (tx*4 + j) : (64 + tx*4 + (j-4)));
            C[(size_t)gm*N + gn] = acc[i][j] + bias[gn];
        }
    }
}

// ---------------------------------------------------------------------------
// Persistent tc encoder layer: 64 steps, one launch, 88 blocks, global barrier.
// ---------------------------------------------------------------------------
__global__ void __launch_bounds__(256, 1) enc_tc_k(
    const float* __restrict__ X,
    const __nv_bfloat16* __restrict__ WHi, const __nv_bfloat16* __restrict__ WLo,
    float* __restrict__ Y, float* __restrict__ Cfin,
    __nv_bfloat16* __restrict__ Hhi, __nv_bfloat16* __restrict__ Hlo,
    int writeY)
{
    uint32_t* sB = sdyn;
    uint32_t* sA = sdyn + SB_WORDS;
    const int tid = threadIdx.x;
    const int lane = tid & 31, wid = tid >> 5;
    const int wm = wid & 1, wn = wid >> 1;
    const int g = lane >> 2, q = lane & 3;
    const int rt = blockIdx.x % 11, ct = blockIdx.x / 11;
    const int m0 = rt*ER, n0 = ct*EC;
    const unsigned nb = gridDim.x;
    unsigned round = 0;

    for (int i = tid; i < 2*128*32; i += 256){
        int s = i >> 12;
        int rem = i & 4095;
        int row = rem >> 5, w4 = rem & 31;
        const uint4* src = reinterpret_cast<const uint4*>(
            (s ? WLo : WHi) + (size_t)(n0 + row)*HH) + w4;
        *reinterpret_cast<uint4*>(&sB[s*128*BP + row*BP + w4*4]) = *src;
    }
    __syncthreads();

    const int hg = ct*32 + wn*8 + q*2;
    float c[8];
    #pragma unroll
    for (int e = 0; e < 8; e++) c[e] = 0.f;

    for (int t = 0; t < 64; t++){
        float2 xv[2][2][4];
        #pragma unroll
        for (int fm = 0; fm < 2; fm++)
            #pragma unroll
            for (int rr = 0; rr < 2; rr++){
                int rglob = m0 + wm*32 + fm*16 + g + rr*8;
                const float* xp = X + ((size_t)t*GT + rglob)*NG + n0 + wn*32 + q*2;
                xv[fm][rr][0] = __ldcg(reinterpret_cast<const float2*>(xp));
                xv[fm][rr][1] = __ldcg(reinterpret_cast<const float2*>(xp + 8));
                xv[fm][rr][2] = __ldcg(reinterpret_cast<const float2*>(xp + 16));
                xv[fm][rr][3] = __ldcg(reinterpret_cast<const float2*>(xp + 24));
            }
        float acc[2][4][4];
        #pragma unroll
        for (int i = 0; i < 2; i++)
            #pragma unroll
            for (int j = 0; j < 4; j++){ acc[i][j][0]=0.f; acc[i][j][1]=0.f; acc[i][j][2]=0.f; acc[i][j][3]=0.f; }
        if (t > 0){
            for (int i = tid; i < 2*64*32; i += 256){
                int s = i >> 11;
                int rem = i & 2047;
                int row = rem >> 5, w4 = rem & 31;
                const uint4* src = reinterpret_cast<const uint4*>(
                    (s ? Hlo : Hhi) + ((size_t)(t-1)*GT + m0 + row)*HH) + w4;
                uint4 v = __ldcg(src);
                *reinterpret_cast<uint4*>(&sA[s*64*AP + row*AP + w4*4]) = v;
            }
            __syncthreads();
            #pragma unroll
            for (int ks = 0; ks < 16; ks++){
                const int kp = ks*8 + q;
                uint32_t a[2][2][4];
                #pragma unroll
                for (int fm = 0; fm < 2; fm++){
                    int row = wm*32 + fm*16;
                    #pragma unroll
                    for (int s = 0; s < 2; s++){
                        const uint32_t* base = sA + s*64*AP;
                        a[fm][s][0] = base[(row+g)*AP + kp];
                        a[fm][s][1] = base[(row+g+8)*AP + kp];
                        a[fm][s][2] = base[(row+g)*AP + kp+4];
                        a[fm][s][3] = base[(row+g+8)*AP + kp+4];
                    }
                }
                #pragma unroll
                for (int fn = 0; fn < 4; fn++){
                    int nr = wn*32 + fn*8 + g;
                    uint32_t bh0 = sB[nr*BP + kp], bh1 = sB[nr*BP + kp+4];
                    uint32_t bl0 = sB[128*BP + nr*BP + kp], bl1 = sB[128*BP + nr*BP + kp+4];
                    #pragma unroll
                    for (int fm = 0; fm < 2; fm++){
                        mma_bf16(acc[fm][fn], a[fm][0], bh0, bh1);
                        mma_bf16(acc[fm][fn], a[fm][0], bl0, bl1);
                        mma_bf16(acc[fm][fn], a[fm][1], bh0, bh1);
                    }
                }
            }
        }
        const int doY = (writeY || t == 63);
        #pragma unroll
        for (int fm = 0; fm < 2; fm++){
            #pragma unroll
            for (int rr = 0; rr < 2; rr++){
                int rglob = m0 + wm*32 + fm*16 + g + rr*8;
                int kp = rr*2;
                float gi0 = acc[fm][0][kp]   + xv[fm][rr][0].x;
                float gi1 = acc[fm][0][kp+1] + xv[fm][rr][0].y;
                float gf0 = acc[fm][1][kp]   + xv[fm][rr][1].x;
                float gf1 = acc[fm][1][kp+1] + xv[fm][rr][1].y;
                float gg0 = acc[fm][2][kp]   + xv[fm][rr][2].x;
                float gg1 = acc[fm][2][kp+1] + xv[fm][rr][2].y;
                float go0 = acc[fm][3][kp]   + xv[fm][rr][3].x;
                float go1 = acc[fm][3][kp+1] + xv[fm][rr][3].y;
                int ci = fm*4 + rr*2;
                float c0 = fsig(gf0)*c[ci]   + fsig(gi0)*ftanh(gg0);
                float c1 = fsig(gf1)*c[ci+1] + fsig(gi1)*ftanh(gg1);
                c[ci] = c0; c[ci+1] = c1;
                float h0 = fsig(go0)*ftanh(c0);
                float h1 = fsig(go1)*ftanh(c1);
                size_t yb = ((size_t)t*GT + rglob)*HH + hg;
                if (doY) *reinterpret_cast<float2*>(Y + yb) = make_float2(h0, h1);
                __nv_bfloat16 b0 = __float2bfloat16(h0), b1 = __float2bfloat16(h1);
                __nv_bfloat162 hhv; hhv.x = b0; hhv.y = b1;
                __nv_bfloat162 llv;
                llv.x = __float2bfloat16(h0 - __bfloat162float(b0));
                llv.y = __float2bfloat16(h1 - __bfloat162float(b1));
                *reinterpret_cast<__nv_bfloat162*>(Hhi + yb) = hhv;
                *reinterpret_cast<__nv_bfloat162*>(Hlo + yb) = llv;
            }
        }
        grid_barrier(nb, round);
    }
    #pragma unroll
    for (int fm = 0; fm < 2; fm++)
        #pragma unroll
        for (int rr = 0; rr < 2; rr++){
            int rglob = m0 + wm*32 + fm*16 + g + rr*8;
            int ci = fm*4 + rr*2;
            *reinterpret_cast<float2*>(Cfin + (size_t)rglob*HH + hg) =
                make_float2(c[ci], c[ci+1]);
        }
}

__global__ void snap_k(const float* __restrict__ Yt, const float* __restrict__ C,
                       const int* __restrict__ tord, float* dh, float* dc)
{
    int b = blockIdx.x, h = threadIdx.x;
    int row = (*tord)*64 + b;
    dh[b*HH + h] = Yt[(size_t)row*HH + h];
    dc[b*HH + h] = C[(size_t)row*HH + h];
}

__global__ void attn_k(const float* __restrict__ Y3, const float* __restrict__ attnW,
                       float* __restrict__ attn)
{
    int b = blockIdx.x, tid = threadIdx.x;
    __shared__ float wae[HH];
    __shared__ float sc[GT];
    __shared__ float red[256];
    wae[tid] = attnW[HH + tid];
    __syncthreads();
    for (int idx = tid; idx < GT; idx += 256){
        int g = idx % GG, t = idx / GG;
        const float* row = Y3 + ((size_t)(t*GT + g*64 + b))*HH;
        float s = 0.f;
        #pragma unroll 4
        for (int h = 0; h < HH; h++) s += row[h]*wae[h];
        sc[idx] = s;
    }
    __syncthreads();
    float mx = -1e30f;
    for (int idx = tid; idx < GT; idx += 256) mx = fmaxf(mx, sc[idx]);
    red[tid] = mx; __syncthreads();
    for (int s = 128; s > 0; s >>= 1){ if (tid < s) red[tid] = fmaxf(red[tid], red[tid+s]); __syncthreads(); }
    mx = red[0]; __syncthreads();
    float sm = 0.f;
    for (int idx = tid; idx < GT; idx += 256){ float e = __expf(sc[idx]-mx); sc[idx] = e; sm += e; }
    red[tid] = sm; __syncthreads();
    for (int s = 128; s > 0; s >>= 1){ if (tid < s) red[tid] += red[tid+s]; __syncthreads(); }
    float inv = __fdividef(1.f, red[0]);
    __syncthreads();
    float a0 = 0.f;
    for (int idx = 0; idx < GT; idx++){
        int g = idx % GG, t = idx / GG;
        a0 += sc[idx]*Y3[((size_t)(t*GT + g*64 + b))*HH + tid];
    }
    attn[b*HH + tid] = a0*inv;
}

__global__ void pack_cin_k(const float* dh0, const float* attn, float* cin)
{
    int b = blockIdx.x, k = threadIdx.x;
    cin[b*512 + k] = (k < HH) ? dh0[b*HH + k] : attn[b*HH + (k - HH)];
}

// ---------------------------------------------------------------------------
// Persistent decoder: 64 steps x 4 layers, one launch. 96 blocks, global barrier.
// ---------------------------------------------------------------------------
__global__ __launch_bounds__(256, 2) void dec_persist_k(
    const float* __restrict__ x, const int* __restrict__ tord,
    const float* __restrict__ cnst, const float* __restrict__ cinAll,
    const float* __restrict__ WeT, const float* __restrict__ WihsT,
    float* __restrict__ H1, float* __restrict__ H2,
    const float* __restrict__ outW, const float* __restrict__ outB,
    const float* __restrict__ Wemb, const float* __restrict__ bemb,
    float* __restrict__ dout)
{
    float* sW   = reinterpret_cast<float*>(sdyn);
    float* sInF = sW + DW_F;
    float* sE   = sInF + DIN_F;
    __shared__ float sRed[16][16];
    __shared__ float sOut[16][4];
    const int tid = threadIdx.x;
    const int tx = tid & 31, ty = tid >> 5;
    const int jc = blockIdx.x & 7;
    const int m0 = (blockIdx.x >> 3)*16, j0 = jc*32;
    const unsigned nb = gridDim.x;
    unsigned round = 0;
    const int tordv = *tord;
    const int j = j0 + tx;
    const int wrow = tid >> 5, wc4 = tid & 31;
    const size_t wcol = (size_t)(wc4 >> 3)*HH + j0 + (wc4 & 7)*4;

    for (int t = 0; t < 64; t++){
        if (t == 0){
            for (int idx = tid; idx < 16*128; idx += 256){
                int rr = idx >> 7, e = idx & 127;
                int m = m0 + rr;
                const float* xr = x + (((size_t)((m & 63)*TT_ + 63))*GG + (tordv + (m >> 6)))*FF;
                float v = bemb[e] + xr[0]*Wemb[e*4] + xr[1]*Wemb[e*4+1]
                                  + xr[2]*Wemb[e*4+2] + xr[3]*Wemb[e*4+3];
                sE[rr*128 + e] = fmaxf(v, 0.f);
            }
            __syncthreads();
        } else {
            {
                int r = tid >> 4, sub = tid & 15, o = sub & 3, seg = sub >> 2;
                const float* hrow = H2 + (size_t)(m0 + r)*HH;
                float s = 0.f;
                #pragma unroll 4
                for (int h = seg*64; h < seg*64 + 64; h++)
                    s += __ldcg(hrow + h) * outW[o*HH + h];
                sRed[r][sub] = s;
            }
            __syncthreads();
            if (tid < 64){
                int rr = tid >> 2, oo = tid & 3;
                float v = sRed[rr][oo] + sRed[rr][4+oo] + sRed[rr][8+oo] + sRed[rr][12+oo] + outB[oo];
                sOut[rr][oo] = v;
                if (jc == 0){
                    int m = m0 + rr;
                    dout[(size_t)(m & 63)*(TT_*NT*FF) + (size_t)(t-1)*(NT*FF) + (m >> 6)*FF + oo] = v;
                }
            }
            __syncthreads();
            for (int idx = tid; idx < 16*128; idx += 256){
                int rr = idx >> 7, e = idx & 127;
                float v = bemb[e] + sOut[rr][0]*Wemb[e*4] + sOut[rr][1]*Wemb[e*4+1]
                        + sOut[rr][2]*Wemb[e*4+2] + sOut[rr][3]*Wemb[e*4+3];
                sE[rr*128 + e] = fmaxf(v, 0.f);
            }
            __syncthreads();
        }
        for (int l = 0; l < 4; l++){
            const float* Wt = (l == 0) ? WeT : (WihsT + (size_t)(l-1)*KSZ);
            const int K = (l == 0) ? EE : HH;
            const int nch = K >> 5;
            const float* In = (l == 2) ? H2 : H1;
            float* Ho = (l == 0 || l == 2) ? H1 : H2;
            float4 wreg[4];
            #pragma unroll
            for (int r = 0; r < 4; r++)
                wreg[r] = __ldcg(reinterpret_cast<const float4*>(
                    Wt + (size_t)(wrow + r*8)*NG + wcol));
            if (l > 0){
                #pragma unroll
                for (int r = 0; r < 4; r++){
                    int i = r*256 + tid, row = i >> 6, c4 = i & 63;
                    float4 v = __ldcg(reinterpret_cast<const float4*>(
                        In + (size_t)(m0 + row)*HH + c4*4));
                    *reinterpret_cast<float4*>(&sInF[row*260 + c4*4]) = v;
                }
            }
            #pragma unroll
            for (int r = 0; r < 4; r++)
                *reinterpret_cast<float4*>(&sW[(wrow + r*8)*128 + wc4*4]) = wreg[r];
            __syncthreads();
            float acc[2][4] = {{0.f,0.f,0.f,0.f},{0.f,0.f,0.f,0.f}};
            const float* aIn = (l == 0) ? sE : sInF;
            const int aPitch = (l == 0) ? 128 : 260;
            for (int ch = 0; ch < nch; ch++){
                if (ch + 1 < nch){
                    #pragma unroll
                    for (int r = 0; r < 4; r++)
                        wreg[r] = __ldcg(reinterpret_cast<const float4*>(
                            Wt + (size_t)((ch+1)*32 + wrow + r*8)*NG + wcol));
                }
                const float* wb = sW + (size_t)(ch & 1)*32*128;
                const float* a0p = aIn + (ty*2)*aPitch + ch*32;
                const float* a1p = aIn + (ty*2+1)*aPitch + ch*32;
                #pragma unroll
                for (int kk = 0; kk < 32; kk++){
                    const float* wr = wb + kk*128;
                    float w0 = wr[tx], w1 = wr[32+tx], w2 = wr[64+tx], w3 = wr[96+tx];
                    float a0 = a0p[kk], a1 = a1p[kk];
                    acc[0][0]+=a0*w0; acc[0][1]+=a0*w1; acc[0][2]+=a0*w2; acc[0][3]+=a0*w3;
                    acc[1][0]+=a1*w0; acc[1][1]+=a1*w1; acc[1][2]+=a1*w2; acc[1][3]+=a1*w3;
                }
                if (ch + 1 < nch){
                    #pragma unroll
                    for (int r = 0; r < 4; r++)
                        *reinterpret_cast<float4*>(&sW[((ch+1)&1)*32*128 + (wrow + r*8)*128 + wc4*4]) = wreg[r];
                    __syncthreads();
                }
            }
            const float* cl = cnst + (size_t)l*BB*NG;
            const float* ci = cinAll + (size_t)l*BB*HH;
            #pragma unroll
            for (int rr = 0; rr < 2; rr++){
                int m = m0 + ty*2 + rr, b = m & 63;
                const float* cp = cl + (size_t)b*NG;
                float gi = acc[rr][0] + cp[j];
                float gf = acc[rr][1] + cp[HH + j];
                float gg = acc[rr][2] + cp[2*HH + j];
                float go = acc[rr][3] + cp[3*HH + j];
                float c2 = fsig(gf)*ci[b*HH + j] + fsig(gi)*ftanh(gg);
                Ho[(size_t)m*HH + j] = fsig(go)*ftanh(c2);
            }
            grid_barrier(nb, round);
        }
    }
    {
        int r = tid >> 4, sub = tid & 15, o = sub & 3, seg = sub >> 2;
        const float* hrow = H2 + (size_t)(m0 + r)*HH;
        float s = 0.f;
        #pragma unroll 4
        for (int h = seg*64; h < seg*64 + 64; h++)
            s += __ldcg(hrow + h) * outW[o*HH + h];
        sRed[r][sub] = s;
    }
    __syncthreads();
    if (tid < 64 && jc == 0){
        int rr = tid >> 2, oo = tid & 3;
        float v = sRed[rr][oo] + sRed[rr][4+oo] + sRed[rr][8+oo] + sRed[rr][12+oo] + outB[oo];
        int m = m0 + rr;
        dout[(size_t)(m & 63)*(TT_*NT*FF) + 63u*(NT*FF) + (m >> 6)*FF + oo] = v;
    }
}

static float* symaddr(const void* sym)
{
    void* p = nullptr;
    cudaGetSymbolAddress(&p, sym);
    return (float*)p;
}

extern "C" void kernel_launch(void* const* d_in, const int* in_sizes, int n_in,
                              void* d_out, int out_size)
{
    (void)in_sizes; (void)n_in; (void)out_size;
    const float* x       = (const float*)d_in[0];
    const float* encLinW = (const float*)d_in[2];
    const float* encLinB = (const float*)d_in[3];
    const float* encWih0 = (const float*)d_in[4];
    const float* encWihs = (const float*)d_in[5];
    const float* encWhh  = (const float*)d_in[6];
    const float* encBih  = (const float*)d_in[7];
    const float* encBhh  = (const float*)d_in[8];
    const float* decEmbW = (const float*)d_in[9];
    const float* decEmbB = (const float*)d_in[10];
    const float* attnW   = (const float*)d_in[11];
    const float* decWih0 = (const float*)d_in[13];
    const float* decWihs = (const float*)d_in[14];
    const float* decWhh  = (const float*)d_in[15];
    const float* decBih  = (const float*)d_in[16];
    const float* decBhh  = (const float*)d_in[17];
    const float* outW    = (const float*)d_in[18];
    const float* outB    = (const float*)d_in[19];
    const int*   tord    = (const int*)d_in[20];
    float* out = (float*)d_out;

    float* pX = symaddr(g_X);
    float* pY = symaddr(g_Y0);
    float* pC = symaddr(g_Cst);
    __nv_bfloat16* pAhi = (__nv_bfloat16*)symaddr(g_Ahi);
    __nv_bfloat16* pAlo = (__nv_bfloat16*)symaddr(g_Alo);
    __nv_bfloat16* pWihHi = (__nv_bfloat16*)symaddr(g_WihHi);
    __nv_bfloat16* pWihLo = (__nv_bfloat16*)symaddr(g_WihLo);
    __nv_bfloat16* pWhhHi = (__nv_bfloat16*)symaddr(g_WhhHi);
    __nv_bfloat16* pWhhLo = (__nv_bfloat16*)symaddr(g_WhhLo);
    float* pBiasEncP = symaddr(g_biasEncP);
    float* pDecWihsT = symaddr(g_decWihsT);
    float* pDecWhhT = symaddr(g_decWhhT);
    float* pPack = symaddr(g_WcPack);
    float* pWeT = symaddr(g_decWeT);
    float* pBiasDec = symaddr(g_biasDec);
    float* pDech = symaddr(g_dech);
    float* pDecc = symaddr(g_decc);
    float* pAttn = symaddr(g_attn);
    float* pCin = symaddr(g_cin);
    float* pConst = symaddr(g_const);
    float* pH1 = symaddr(g_h1);
    float* pH2 = symaddr(g_h2);

    cudaFuncSetAttribute(enc_tc_k, cudaFuncAttributeMaxDynamicSharedMemorySize, SMEM_ENC);
    cudaFuncSetAttribute(dec_persist_k, cudaFuncAttributeMaxDynamicSharedMemorySize, SMEM_DEC);
    cudaFuncSetAttribute(gemm_tc_k, cudaFuncAttributeMaxDynamicSharedMemorySize, SMEM_GEMM);

    dim3 tb(32, 8);
    wsplit_perm_k<<<(NG*EE + 255)/256, 256>>>(encWih0, EE, pWihHi, pWihLo);
    for (int l = 1; l < 4; l++)
        wsplit_perm_k<<<(NG*HH + 255)/256, 256>>>(encWihs + (size_t)(l-1)*NG*HH, HH,
                                                  pWihHi + NG*EE + (size_t)(l-1)*NG*HH,
                                                  pWihLo + NG*EE + (size_t)(l-1)*NG*HH);
    for (int l = 0; l < 4; l++)
        wsplit_perm_k<<<(NG*HH + 255)/256, 256>>>(encWhh + (size_t)l*NG*HH, HH,
                                                  pWhhHi + (size_t)l*NG*HH,
                                                  pWhhLo + (size_t)l*NG*HH);
    for (int l = 0; l < 4; l++)
        addv_perm_k<<<4, 256>>>(encBih + l*NG, encBhh + l*NG, pBiasEncP + l*NG);
    for (int l = 0; l < 3; l++)
        transpose_k<<<dim3(8, 32), tb>>>(decWihs + (size_t)l*NG*HH, HH, NG, HH, pDecWihsT + (size_t)l*KSZ, NG);
    for (int l = 1; l < 4; l++)
        transpose_k<<<dim3(8, 32), tb>>>(decWhh + (size_t)l*NG*HH, HH, NG, HH, pDecWhhT + (size_t)(l-1)*KSZ, NG);
    transpose_k<<<dim3(8, 32), tb>>>(decWhh, HH, NG, HH, pPack, NG);
    transpose_k<<<dim3(8, 32), tb>>>(decWih0, 384, NG, HH, pPack + (size_t)HH*NG, NG);
    transpose_k<<<dim3(4, 32), tb>>>(decWih0 + HH, 384, NG, EE, pWeT, NG);
    addv_k<<<16, 256>>>(decBih, decBhh, pBiasDec, 4*NG);

    emb_k<<<MTOT, 128>>>(x, encLinW, encLinB, pAhi, pAlo);

    for (int l = 0; l < 4; l++){
        const __nv_bfloat16* wh = (l == 0) ? pWihHi : (pWihHi + NG*EE + (size_t)(l-1)*NG*HH);
        const __nv_bfloat16* wl = (l == 0) ? pWihLo : (pWihLo + NG*EE + (size_t)(l-1)*NG*HH);
        int Kin = (l == 0) ? EE : HH;
        gemm_tc_k<<<dim3(8, MTOT/128), 256, SMEM_GEMM>>>(pAhi, pAlo, wh, wl,
                                                         pBiasEncP + l*NG, pX, Kin);
        reset_barrier_k<<<1, 1>>>();
        enc_tc_k<<<88, 256, SMEM_ENC>>>(pX, pWhhHi + (size_t)l*NG*HH, pWhhLo + (size_t)l*NG*HH,
                                        pY, pC, pAhi, pAlo, (l == 3) ? 1 : 0);
        snap_k<<<64, 256>>>(pY + (size_t)(TT_-1)*GT*HH, pC, tord,
                            pDech + (size_t)l*BB*HH, pDecc + (size_t)l*BB*HH);
    }

    attn_k<<<BB, 256>>>(pY, attnW, pAttn);
    pack_cin_k<<<BB, 512>>>(pDech, pAttn, pCin);
    gemm_k<<<dim3(8, 1), 256>>>(pCin, pPack, pBiasDec, pConst, BB, NG, 512);
    for (int l = 1; l < 4; l++)
        gemm_k<<<dim3(8, 1), 256>>>(pDech + (size_t)l*BB*HH, pDecWhhT + (size_t)(l-1)*KSZ,
                                    pBiasDec + l*NG, pConst + (size_t)l*BB*NG, BB, NG, HH);

    reset_barrier_k<<<1, 1>>>();
    dec_persist_k<<<96, 256, SMEM_DEC>>>(x, tord, pConst, pDecc, pWeT, pDecWihsT,
                                         pH1, pH2, outW, outB, decEmbW, decEmbB, out);
}